// round 7
// baseline (speedup 1.0000x reference)
#include <cuda_runtime.h>
#include <cstdint>

// Depthwise 3D conv 3x3x3, SAME, stride 1.
// x: (N=4, D=16, H=112, W=112, C=64) f32, NDHWC
// w: (3,3,3,1,64) f32 -> idx ((kd*3+kh)*3+kw)*64 + c
//
// Thread: 2 channels (f32x2), 8 w-outputs, 2 h-rows.
// R7 vs R6: __launch_bounds__(128,7) (72-reg cap -> 7 blocks/SM, 43.75% occ)
// plus register diet (32-bit offsets off one base pointer, single weight
// rotation site) so the squeeze lands on addressing, not the rv[10] batch.

#define N_  4
#define D_  16
#define H_  112
#define W_  112
#define C_  64
#define WPT 8
#define CS  (C_ / 2)   // 32 ull per spatial position

typedef unsigned long long ull;

__device__ __forceinline__ ull ffma2(ull a, ull b, ull c) {
    ull d;
    asm("fma.rn.f32x2 %0, %1, %2, %3;" : "=l"(d) : "l"(a), "l"(b), "l"(c));
    return d;
}

__global__ void __launch_bounds__(128, 7)
dwconv3d_kernel(const float* __restrict__ x,
                const float* __restrict__ wgt,
                float* __restrict__ out) {
    __shared__ float swf[27 * C_];

    const int tid = threadIdx.y * 32 + threadIdx.x;
    for (int i = tid; i < 27 * C_ / 4; i += 128)
        reinterpret_cast<float4*>(swf)[i] =
            reinterpret_cast<const float4*>(wgt)[i];
    __syncthreads();

    const ull* __restrict__ swp = reinterpret_cast<const ull*>(swf);

    const int tx = threadIdx.x;                       // channel pair 0..31
    const int h0 = blockIdx.y * 8 + threadIdx.y * 2;  // even rows 0..110
    const int w0 = blockIdx.x * WPT;                  // 0..104
    const int nd = blockIdx.z;
    const int n  = nd >> 4;
    const int d  = nd & 15;

    const bool wlo = (w0 > 0);
    const bool whi = (w0 + WPT < W_);   // zw = w0+8 in range?

    ull acc0[WPT], acc1[WPT];
#pragma unroll
    for (int i = 0; i < WPT; i++) { acc0[i] = 0ull; acc1[i] = 0ull; }

    // One base pointer at (n, d-1, h0-1, w0, tx); 32-bit offsets from here.
    const ull* __restrict__ base =
        reinterpret_cast<const ull*>(x) +
        ((((n * D_ + (d - 1)) * H_ + (h0 - 1)) * W_ + w0) * CS + tx);

    const int rowStep   = W_ * CS;            // one h row
    const int sliceStep = H_ * W_ * CS;       // one d slice

#pragma unroll
    for (int kd = 0; kd < 3; kd++) {
        const int zd = d + kd - 1;
        if ((unsigned)zd >= D_) continue;

        int off = kd * sliceStep;             // row (kd, r=0) offset

        // weight rotation: wa = taps (kd, kh=r), wb = (kd, kh=r-1)
        ull wa0 = 0, wa1 = 0, wa2 = 0;
        ull wb0, wb1, wb2;

#pragma unroll
        for (int r = 0; r < 4; r++) {          // zh = h0-1 .. h0+2
            const int zh = h0 - 1 + r;
            const bool rowOk = ((unsigned)zh < H_);

            ull rv[WPT + 2];
            if (rowOk) {
                // --- batched row preload: 10 independent LDGs ---
                rv[0] = wlo ? base[off - CS] : 0ull;
#pragma unroll
                for (int j = 0; j < WPT; j++)
                    rv[j + 1] = base[off + j * CS];
                rv[WPT + 1] = whi ? base[off + WPT * CS] : 0ull;
            }

            // --- weight rotate + fetch (single site; LDS drains under LDG) ---
            wb0 = wa0; wb1 = wa1; wb2 = wa2;
            if (r < 3) {
                const int wbase = (kd * 9 + r * 3) * CS + tx;
                wa0 = swp[wbase];
                wa1 = swp[wbase + CS];
                wa2 = swp[wbase + 2 * CS];
            }

            if (rowOk) {
                // --- register-only FMA burst ---
#pragma unroll
                for (int i = 0; i < WPT; i++) {
                    if (r <= 2) {                          // output h0, kh=r
                        acc0[i] = ffma2(rv[i],     wa0, acc0[i]);
                        acc0[i] = ffma2(rv[i + 1], wa1, acc0[i]);
                        acc0[i] = ffma2(rv[i + 2], wa2, acc0[i]);
                    }
                    if (r >= 1) {                          // output h0+1, kh=r-1
                        acc1[i] = ffma2(rv[i],     wb0, acc1[i]);
                        acc1[i] = ffma2(rv[i + 1], wb1, acc1[i]);
                        acc1[i] = ffma2(rv[i + 2], wb2, acc1[i]);
                    }
                }
            }
            off += rowStep;
        }
    }

    ull* __restrict__ op =
        reinterpret_cast<ull*>(out) +
        ((((n * D_ + d) * H_ + h0) * W_ + w0) * CS + tx);
#pragma unroll
    for (int i = 0; i < WPT; i++) {
        op[i * CS] = acc0[i];
        op[W_ * CS + i * CS] = acc1[i];
    }
}

extern "C" void kernel_launch(void* const* d_in, const int* in_sizes, int n_in,
                              void* d_out, int out_size) {
    const float* x = (const float*)d_in[0];
    const float* w = (const float*)d_in[1];
    float* o = (float*)d_out;

    dim3 block(32, 4, 1);                        // 128 threads
    dim3 grid(W_ / WPT, H_ / 8, N_ * D_);        // 14 x 14 x 64
    dwconv3d_kernel<<<grid, block>>>(x, w, o);
}

// round 8
// speedup vs baseline: 1.1098x; 1.1098x over previous
#include <cuda_runtime.h>
#include <cstdint>

// Depthwise 3D conv 3x3x3, SAME, stride 1.
// x: (N=4, D=16, H=112, W=112, C=64) f32, NDHWC
// w: (3,3,3,1,64) f32 -> idx ((kd*3+kh)*3+kw)*64 + c
//
// Thread: 2 channels (f32x2), 8 w-outputs, 2 h-rows. R6 inner schedule
// (batched rv[10] LDG burst -> weight fetch -> 48 packed FMA, per-row pointer
// with constant immediate offsets).
// R8 vs R6: no smem — weights read via direct LDG (L1-resident, 6.9KB);
// 64-thread blocks with __launch_bounds__(64,13): 78-reg cap == natural
// demand, 13 blocks/SM -> 26 warps (vs 24).

#define N_  4
#define D_  16
#define H_  112
#define W_  112
#define C_  64
#define WPT 8
#define CS  (C_ / 2)   // 32 ull per spatial position

typedef unsigned long long ull;

__device__ __forceinline__ ull ffma2(ull a, ull b, ull c) {
    ull d;
    asm("fma.rn.f32x2 %0, %1, %2, %3;" : "=l"(d) : "l"(a), "l"(b), "l"(c));
    return d;
}

__global__ void __launch_bounds__(64, 13)
dwconv3d_kernel(const float* __restrict__ x,
                const float* __restrict__ wgt,
                float* __restrict__ out) {
    const ull* __restrict__ swp = reinterpret_cast<const ull*>(wgt);

    const int tx = threadIdx.x;                       // channel pair 0..31
    const int h0 = blockIdx.y * 4 + threadIdx.y * 2;  // even rows 0..110
    const int w0 = blockIdx.x * WPT;                  // 0..104
    const int nd = blockIdx.z;
    const int n  = nd >> 4;
    const int d  = nd & 15;

    const bool wlo = (w0 > 0);
    const bool whi = (w0 + WPT < W_);   // zw = w0+8 in range?

    ull acc0[WPT], acc1[WPT];
#pragma unroll
    for (int i = 0; i < WPT; i++) { acc0[i] = 0ull; acc1[i] = 0ull; }

    const ull* __restrict__ xp = reinterpret_cast<const ull*>(x);

#pragma unroll
    for (int kd = 0; kd < 3; kd++) {
        const int zd = d + kd - 1;
        if ((unsigned)zd >= D_) continue;

        // pointer to (n, zd, h0-1, w0, tx); advances one h-row per r
        const ull* rowp =
            xp + ((((n * D_ + zd) * H_ + (h0 - 1)) * W_ + w0) * CS + tx);

        // weight rotation: wa = taps (kd, kh=r), wb = (kd, kh=r-1)
        ull wa0 = 0, wa1 = 0, wa2 = 0;
        ull wb0, wb1, wb2;

#pragma unroll
        for (int r = 0; r < 4; r++) {          // zh = h0-1 .. h0+2
            const int zh = h0 - 1 + r;
            if ((unsigned)zh < H_) {
                const ull* __restrict__ p = rowp;

                // --- batched row preload first: 10 independent LDGs,
                //     constant immediate offsets off the row pointer ---
                ull rv[WPT + 2];
                rv[0] = wlo ? p[-CS] : 0ull;
#pragma unroll
                for (int j = 0; j < WPT; j++)
                    rv[j + 1] = p[j * CS];
                rv[WPT + 1] = whi ? p[WPT * CS] : 0ull;

                // --- weight rotate + fetch (LDG, L1-resident; drains
                //     under the rv LDG latency) ---
                wb0 = wa0; wb1 = wa1; wb2 = wa2;
                if (r < 3) {
                    const int base = (kd * 9 + r * 3) * CS + tx;
                    wa0 = swp[base];
                    wa1 = swp[base + CS];
                    wa2 = swp[base + 2 * CS];
                }

                // --- register-only FMA burst ---
#pragma unroll
                for (int i = 0; i < WPT; i++) {
                    if (r <= 2) {                          // output h0, kh=r
                        acc0[i] = ffma2(rv[i],     wa0, acc0[i]);
                        acc0[i] = ffma2(rv[i + 1], wa1, acc0[i]);
                        acc0[i] = ffma2(rv[i + 2], wa2, acc0[i]);
                    }
                    if (r >= 1) {                          // output h0+1, kh=r-1
                        acc1[i] = ffma2(rv[i],     wb0, acc1[i]);
                        acc1[i] = ffma2(rv[i + 1], wb1, acc1[i]);
                        acc1[i] = ffma2(rv[i + 2], wb2, acc1[i]);
                    }
                }
            } else {
                // row out of range: still rotate weights to keep tap alignment
                wb0 = wa0; wb1 = wa1; wb2 = wa2;
                if (r < 3) {
                    const int base = (kd * 9 + r * 3) * CS + tx;
                    wa0 = swp[base];
                    wa1 = swp[base + CS];
                    wa2 = swp[base + 2 * CS];
                }
            }
            rowp += W_ * CS;
        }
    }

    ull* __restrict__ op =
        reinterpret_cast<ull*>(out) +
        ((((n * D_ + d) * H_ + h0) * W_ + w0) * CS + tx);
#pragma unroll
    for (int i = 0; i < WPT; i++) {
        op[i * CS] = acc0[i];
        op[W_ * CS + i * CS] = acc1[i];
    }
}

extern "C" void kernel_launch(void* const* d_in, const int* in_sizes, int n_in,
                              void* d_out, int out_size) {
    const float* x = (const float*)d_in[0];
    const float* w = (const float*)d_in[1];
    float* o = (float*)d_out;

    dim3 block(32, 2, 1);                        // 64 threads
    dim3 grid(W_ / WPT, H_ / 4, N_ * D_);        // 14 x 28 x 64
    dwconv3d_kernel<<<grid, block>>>(x, w, o);
}

// round 9
// speedup vs baseline: 1.1828x; 1.0657x over previous
#include <cuda_runtime.h>
#include <cstdint>

// Depthwise 3D conv 3x3x3, SAME, stride 1.
// x: (N=4, D=16, H=112, W=112, C=64) f32, NDHWC
// w: (3,3,3,1,64) f32 -> idx ((kd*3+kh)*3+kw)*64 + c
//
// Thread: 2 channels (f32x2), 8 w-outputs, 2 h-rows. R8 schedule per row:
// batched rv[10] LDG burst -> weight LDG (L1-resident) -> 48 packed FMA.
// R9 vs R8: block-uniform interior/edge split. Interior blocks (~70%) run a
// guard-free body (no zd/zh checks, unconditional halo loads) so ptxas can
// software-pipeline across all 12 rows; edge blocks run the guarded body.

#define N_  4
#define D_  16
#define H_  112
#define W_  112
#define C_  64
#define WPT 8
#define CS  (C_ / 2)   // 32 ull per spatial position

typedef unsigned long long ull;

__device__ __forceinline__ ull ffma2(ull a, ull b, ull c) {
    ull d;
    asm("fma.rn.f32x2 %0, %1, %2, %3;" : "=l"(d) : "l"(a), "l"(b), "l"(c));
    return d;
}

template <bool INT>
__device__ __forceinline__ void conv_body(
    const ull* __restrict__ xp, const ull* __restrict__ swp,
    ull* __restrict__ out, int n, int d, int h0, int w0, int tx) {

    const bool wlo = INT || (w0 > 0);
    const bool whi = INT || (w0 + WPT < W_);

    ull acc0[WPT], acc1[WPT];
#pragma unroll
    for (int i = 0; i < WPT; i++) { acc0[i] = 0ull; acc1[i] = 0ull; }

#pragma unroll
    for (int kd = 0; kd < 3; kd++) {
        const int zd = d + kd - 1;
        if (!INT && (unsigned)zd >= D_) continue;

        // pointer to (n, zd, h0-1, w0, tx); advances one h-row per r
        const ull* rowp =
            xp + ((((n * D_ + zd) * H_ + (h0 - 1)) * W_ + w0) * CS + tx);

        // weight rotation: wa = taps (kd, kh=r), wb = (kd, kh=r-1)
        ull wa0 = 0, wa1 = 0, wa2 = 0;
        ull wb0, wb1, wb2;

#pragma unroll
        for (int r = 0; r < 4; r++) {          // zh = h0-1 .. h0+2
            const int zh = h0 - 1 + r;
            const bool rowOk = INT || ((unsigned)zh < H_);

            ull rv[WPT + 2];
            if (rowOk) {
                // batched row preload: 10 LDGs, immediate offsets
                rv[0] = wlo ? rowp[-CS] : 0ull;
#pragma unroll
                for (int j = 0; j < WPT; j++)
                    rv[j + 1] = rowp[j * CS];
                rv[WPT + 1] = whi ? rowp[WPT * CS] : 0ull;
            }

            // weight rotate + fetch (drains under LDG latency)
            wb0 = wa0; wb1 = wa1; wb2 = wa2;
            if (r < 3) {
                const int base = (kd * 9 + r * 3) * CS + tx;
                wa0 = swp[base];
                wa1 = swp[base + CS];
                wa2 = swp[base + 2 * CS];
            }

            if (rowOk) {
                // register-only FMA burst
#pragma unroll
                for (int i = 0; i < WPT; i++) {
                    if (r <= 2) {                          // output h0, kh=r
                        acc0[i] = ffma2(rv[i],     wa0, acc0[i]);
                        acc0[i] = ffma2(rv[i + 1], wa1, acc0[i]);
                        acc0[i] = ffma2(rv[i + 2], wa2, acc0[i]);
                    }
                    if (r >= 1) {                          // output h0+1, kh=r-1
                        acc1[i] = ffma2(rv[i],     wb0, acc1[i]);
                        acc1[i] = ffma2(rv[i + 1], wb1, acc1[i]);
                        acc1[i] = ffma2(rv[i + 2], wb2, acc1[i]);
                    }
                }
            }
            rowp += W_ * CS;
        }
    }

    ull* __restrict__ op =
        out + ((((n * D_ + d) * H_ + h0) * W_ + w0) * CS + tx);
#pragma unroll
    for (int i = 0; i < WPT; i++) {
        op[i * CS] = acc0[i];
        op[W_ * CS + i * CS] = acc1[i];
    }
}

__global__ void __launch_bounds__(64, 13)
dwconv3d_kernel(const float* __restrict__ x,
                const float* __restrict__ wgt,
                float* __restrict__ out) {
    const ull* __restrict__ swp = reinterpret_cast<const ull*>(wgt);
    const ull* __restrict__ xp  = reinterpret_cast<const ull*>(x);
    ull* __restrict__ op        = reinterpret_cast<ull*>(out);

    const int tx = threadIdx.x;                       // channel pair 0..31
    const int h0 = blockIdx.y * 4 + threadIdx.y * 2;  // even rows 0..110
    const int w0 = blockIdx.x * WPT;                  // 0..104
    const int nd = blockIdx.z;
    const int n  = nd >> 4;
    const int d  = nd & 15;

    // Block-uniform interior test: no d/h/w halo clamping anywhere in block.
    const bool interior =
        (d >= 1) && (d <= 14) &&
        (blockIdx.y >= 1) && (blockIdx.y <= (H_ / 4) - 2) &&
        (blockIdx.x >= 1) && (blockIdx.x <= (W_ / WPT) - 2);

    if (interior)
        conv_body<true>(xp, swp, op, n, d, h0, w0, tx);
    else
        conv_body<false>(xp, swp, op, n, d, h0, w0, tx);
}

extern "C" void kernel_launch(void* const* d_in, const int* in_sizes, int n_in,
                              void* d_out, int out_size) {
    const float* x = (const float*)d_in[0];
    const float* w = (const float*)d_in[1];
    float* o = (float*)d_out;

    dim3 block(32, 2, 1);                        // 64 threads
    dim3 grid(W_ / WPT, H_ / 4, N_ * D_);        // 14 x 28 x 64
    dwconv3d_kernel<<<grid, block>>>(x, w, o);
}